// round 1
// baseline (speedup 1.0000x reference)
#include <cuda_runtime.h>

// SelfNorm: out[b,c,h,w] = x*std_w + mean*(mean_w - std_w)
// where mean/std are per-(b,c) over HW, and mean_w/std_w come from tiny
// 2->16->1 MLPs (relu hidden, sigmoid output) on [mean, std].

#define HW 3136          // 56*56
#define F4 784           // HW/4
#define NTHREADS 256
#define EPS 1e-5f

__device__ __forceinline__ float tiny_mlp(float mean, float std,
                                          const float* __restrict__ W1,
                                          const float* __restrict__ b1,
                                          const float* __restrict__ W2,
                                          const float* __restrict__ b2) {
    float z = b2[0];
    #pragma unroll
    for (int o = 0; o < 16; o++) {
        float h = fmaf(W1[2 * o], mean, fmaf(W1[2 * o + 1], std, b1[o]));
        h = fmaxf(h, 0.0f);
        z = fmaf(W2[o], h, z);
    }
    // sigmoid
    return 1.0f / (1.0f + __expf(-z));
}

__global__ void __launch_bounds__(NTHREADS)
selfnorm_kernel(const float4* __restrict__ x,
                const float* __restrict__ W1m, const float* __restrict__ b1m,
                const float* __restrict__ W2m, const float* __restrict__ b2m,
                const float* __restrict__ W1s, const float* __restrict__ b1s,
                const float* __restrict__ W2s, const float* __restrict__ b2s,
                float4* __restrict__ out) {
    const int row = blockIdx.x;               // b*256 + c
    const int t   = threadIdx.x;
    const int lane = t & 31;
    const int wid  = t >> 5;

    const float4* __restrict__ xr = x + (size_t)row * F4;
    float4*       __restrict__ orow = out + (size_t)row * F4;

    // Load the whole row into registers; accumulate sum and sum-of-squares.
    float4 v[4];
    float s = 0.0f, sq = 0.0f;
    #pragma unroll
    for (int i = 0; i < 4; i++) {
        int id = t + NTHREADS * i;
        if (id < F4) {
            float4 a = xr[id];
            v[i] = a;
            s += a.x + a.y + a.z + a.w;
            sq = fmaf(a.x, a.x, sq);
            sq = fmaf(a.y, a.y, sq);
            sq = fmaf(a.z, a.z, sq);
            sq = fmaf(a.w, a.w, sq);
        }
    }

    // Warp reduce
    #pragma unroll
    for (int o = 16; o > 0; o >>= 1) {
        s  += __shfl_down_sync(0xffffffffu, s,  o);
        sq += __shfl_down_sync(0xffffffffu, sq, o);
    }

    __shared__ float ss[8], ssq[8];
    __shared__ float sAlpha, sBeta;
    if (lane == 0) { ss[wid] = s; ssq[wid] = sq; }
    __syncthreads();

    if (t == 0) {
        float ts = 0.0f, tsq = 0.0f;
        #pragma unroll
        for (int i = 0; i < 8; i++) { ts += ss[i]; tsq += ssq[i]; }
        const float n = (float)HW;
        float mean = ts / n;
        float var  = (tsq - n * mean * mean) / (n - 1.0f);
        var = fmaxf(var, 0.0f);
        float std = sqrtf(var + EPS);

        float mean_w = tiny_mlp(mean, std, W1m, b1m, W2m, b2m);
        float std_w  = tiny_mlp(mean, std, W1s, b1s, W2s, b2s);

        sAlpha = std_w;
        sBeta  = mean * (mean_w - std_w);
    }
    __syncthreads();

    const float alpha = sAlpha;
    const float beta  = sBeta;

    // Write transformed row from registers.
    #pragma unroll
    for (int i = 0; i < 4; i++) {
        int id = t + NTHREADS * i;
        if (id < F4) {
            float4 a = v[i];
            float4 r;
            r.x = fmaf(a.x, alpha, beta);
            r.y = fmaf(a.y, alpha, beta);
            r.z = fmaf(a.z, alpha, beta);
            r.w = fmaf(a.w, alpha, beta);
            orow[id] = r;
        }
    }
}

extern "C" void kernel_launch(void* const* d_in, const int* in_sizes, int n_in,
                              void* d_out, int out_size) {
    const float4* x  = (const float4*)d_in[0];
    const float* W1m = (const float*)d_in[1];
    const float* b1m = (const float*)d_in[2];
    const float* W2m = (const float*)d_in[3];
    const float* b2m = (const float*)d_in[4];
    const float* W1s = (const float*)d_in[5];
    const float* b1s = (const float*)d_in[6];
    const float* W2s = (const float*)d_in[7];
    const float* b2s = (const float*)d_in[8];
    float4* out = (float4*)d_out;

    const int rows = 32 * 256;  // B * C
    selfnorm_kernel<<<rows, NTHREADS>>>(x, W1m, b1m, W2m, b2m,
                                        W1s, b1s, W2s, b2s, out);
}